// round 1
// baseline (speedup 1.0000x reference)
#include <cuda_runtime.h>
#include <math.h>

#define HIDDEN 768
#define NH     12
#define HEAD   64
#define BATCH  2
#define SEQ    2048
#define M_TOT  (BATCH * SEQ)     // 4096
#define QKV_N  (3 * HIDDEN)      // 2304

// Scratch (allocation-free rule: __device__ globals)
__device__ float g_qkv[(size_t)M_TOT * QKV_N];   // [4096][2304]
__device__ float g_att[(size_t)M_TOT * HIDDEN];  // [4096][768]

// ---------------------------------------------------------------------------
// Tiled GEMM with bias: C[M][N] = A[M][K] @ B[K][N] + bias[N]
// BM=BN=128, BK=16, 256 threads, 8x8 register tile per thread.
// ---------------------------------------------------------------------------
__global__ __launch_bounds__(256, 2)
void gemm_bias(const float* __restrict__ A, const float* __restrict__ Bm,
               const float* __restrict__ bias, float* __restrict__ C,
               int M, int Nn, int K)
{
    __shared__ float As[16][128];   // k-major (transposed A tile)
    __shared__ float Bs[16][128];

    const int tid = threadIdx.x;
    const int tx  = tid & 15;
    const int ty  = tid >> 4;
    const int m0  = blockIdx.y * 128;
    const int n0  = blockIdx.x * 128;

    float acc[8][8];
#pragma unroll
    for (int i = 0; i < 8; i++)
#pragma unroll
        for (int j = 0; j < 8; j++) acc[i][j] = 0.f;

    for (int k0 = 0; k0 < K; k0 += 16) {
        // A tile: 128m x 16k, store transposed
#pragma unroll
        for (int it = 0; it < 2; it++) {
            int f = tid + 256 * it;          // 0..511 float4s
            int m = f >> 2;
            int k = (f & 3) << 2;
            float4 a = *(const float4*)&A[(size_t)(m0 + m) * K + k0 + k];
            As[k + 0][m] = a.x;
            As[k + 1][m] = a.y;
            As[k + 2][m] = a.z;
            As[k + 3][m] = a.w;
        }
        // B tile: 16k x 128n, natural layout
#pragma unroll
        for (int it = 0; it < 2; it++) {
            int f  = tid + 256 * it;
            int kk = f >> 5;
            int n  = (f & 31) << 2;
            *(float4*)&Bs[kk][n] =
                *(const float4*)&Bm[(size_t)(k0 + kk) * Nn + n0 + n];
        }
        __syncthreads();

#pragma unroll
        for (int k = 0; k < 16; k++) {
            float4 a0 = *(const float4*)&As[k][ty * 4];
            float4 a1 = *(const float4*)&As[k][64 + ty * 4];
            float4 b0 = *(const float4*)&Bs[k][tx * 4];
            float4 b1 = *(const float4*)&Bs[k][64 + tx * 4];
            float ar[8] = {a0.x, a0.y, a0.z, a0.w, a1.x, a1.y, a1.z, a1.w};
            float br[8] = {b0.x, b0.y, b0.z, b0.w, b1.x, b1.y, b1.z, b1.w};
#pragma unroll
            for (int i = 0; i < 8; i++)
#pragma unroll
                for (int j = 0; j < 8; j++)
                    acc[i][j] += ar[i] * br[j];
        }
        __syncthreads();
    }

#pragma unroll
    for (int i = 0; i < 8; i++) {
        int row = m0 + ((i >> 2) * 64) + ty * 4 + (i & 3);
#pragma unroll
        for (int cg = 0; cg < 2; cg++) {
            int col = n0 + cg * 64 + tx * 4;
            float4 bv = *(const float4*)&bias[col];
            float4 ov;
            ov.x = acc[i][cg * 4 + 0] + bv.x;
            ov.y = acc[i][cg * 4 + 1] + bv.y;
            ov.z = acc[i][cg * 4 + 2] + bv.z;
            ov.w = acc[i][cg * 4 + 3] + bv.w;
            *(float4*)&C[(size_t)row * Nn + col] = ov;
        }
    }
}

// ---------------------------------------------------------------------------
// Flash attention (causal), fp32.
// Block: 128 q-rows x one head. Tiles of 64 kv-cols. 256 threads.
// Per thread: 8 q-rows ({ty*4+i, 64+ty*4+i}) x 4 kv-cols / 4 d-cols.
// Smem: Qs[d][128] (d-major), Ks[d][64] (d-major), Vs[64][64], Ps[128][64].
// ---------------------------------------------------------------------------
__global__ __launch_bounds__(256, 2)
void attn_kernel(const float* __restrict__ qkv, float* __restrict__ out)
{
    extern __shared__ float sm[];
    float* Qs = sm;                 // 64*128
    float* Ks = Qs + 64 * 128;      // 64*64
    float* Vs = Ks + 64 * 64;       // 64*64
    float* Ps = Vs + 64 * 64;       // 128*64

    const int tid = threadIdx.x;
    const int tx  = tid & 15;
    const int ty  = tid >> 4;
    const int qt  = 15 - (int)blockIdx.x;   // heavy tiles first
    const int h   = blockIdx.y;
    const int b   = blockIdx.z;
    const int q0  = qt * 128;

    const size_t base = (size_t)b * SEQ * QKV_N;
    const int qoff = h * HEAD;
    const int koff = HIDDEN + h * HEAD;
    const int voff = 2 * HIDDEN + h * HEAD;

    // Load Q tile transposed: Qs[d][m]
#pragma unroll
    for (int it = 0; it < 8; it++) {
        int f = tid + 256 * it;       // 0..2047 float4s
        int m = f & 127;
        int d = (f >> 7) << 2;
        float4 q = *(const float4*)&qkv[base + (size_t)(q0 + m) * QKV_N + qoff + d];
        Qs[(d + 0) * 128 + m] = q.x;
        Qs[(d + 1) * 128 + m] = q.y;
        Qs[(d + 2) * 128 + m] = q.z;
        Qs[(d + 3) * 128 + m] = q.w;
    }

    float m_i[8], l_i[8], o[8][4];
#pragma unroll
    for (int r = 0; r < 8; r++) {
        m_i[r] = -1e30f;
        l_i[r] = 0.f;
#pragma unroll
        for (int dc = 0; dc < 4; dc++) o[r][dc] = 0.f;
    }

    __syncthreads();

    const int ktiles = 2 * qt + 2;
    for (int kt = 0; kt < ktiles; kt++) {
        const int n0k = kt * 64;

        // K tile transposed: Ks[d][j]
#pragma unroll
        for (int it = 0; it < 4; it++) {
            int f = tid + 256 * it;   // 0..1023 float4s
            int j = f & 63;
            int d = (f >> 6) << 2;
            float4 kv = *(const float4*)&qkv[base + (size_t)(n0k + j) * QKV_N + koff + d];
            Ks[(d + 0) * 64 + j] = kv.x;
            Ks[(d + 1) * 64 + j] = kv.y;
            Ks[(d + 2) * 64 + j] = kv.z;
            Ks[(d + 3) * 64 + j] = kv.w;
        }
        // V tile natural: Vs[j][d]
#pragma unroll
        for (int it = 0; it < 4; it++) {
            int f = tid + 256 * it;
            int j = f >> 4;
            int d = (f & 15) << 2;
            *(float4*)&Vs[j * 64 + d] =
                *(const float4*)&qkv[base + (size_t)(n0k + j) * QKV_N + voff + d];
        }
        __syncthreads();

        // ---- S = Q K^T ----
        float s[8][4];
#pragma unroll
        for (int r = 0; r < 8; r++)
#pragma unroll
            for (int j = 0; j < 4; j++) s[r][j] = 0.f;

#pragma unroll 16
        for (int d = 0; d < 64; d++) {
            float4 qa = *(const float4*)&Qs[d * 128 + ty * 4];
            float4 qb = *(const float4*)&Qs[d * 128 + 64 + ty * 4];
            float4 kk = *(const float4*)&Ks[d * 64 + tx * 4];
            float qv[8] = {qa.x, qa.y, qa.z, qa.w, qb.x, qb.y, qb.z, qb.w};
            float kv[4] = {kk.x, kk.y, kk.z, kk.w};
#pragma unroll
            for (int r = 0; r < 8; r++)
#pragma unroll
                for (int j = 0; j < 4; j++)
                    s[r][j] += qv[r] * kv[j];
        }

        // ---- online softmax ----
        const float scale = 0.125f;   // 1/sqrt(64)
#pragma unroll
        for (int r = 0; r < 8; r++) {
            int rl  = ((r >> 2) * 64) + ty * 4 + (r & 3);
            int row = q0 + rl;
            float mx = -1e30f;
#pragma unroll
            for (int j = 0; j < 4; j++) {
                float v = s[r][j] * scale;
                if (n0k + tx * 4 + j > row) v = -1e30f;   // causal mask
                s[r][j] = v;
                mx = fmaxf(mx, v);
            }
            mx = fmaxf(mx, __shfl_xor_sync(0xffffffffu, mx, 1));
            mx = fmaxf(mx, __shfl_xor_sync(0xffffffffu, mx, 2));
            mx = fmaxf(mx, __shfl_xor_sync(0xffffffffu, mx, 4));
            mx = fmaxf(mx, __shfl_xor_sync(0xffffffffu, mx, 8));

            float mn    = fmaxf(m_i[r], mx);
            float alpha = __expf(m_i[r] - mn);
            m_i[r] = mn;

            float4 p;
            p.x = __expf(s[r][0] - mn);
            p.y = __expf(s[r][1] - mn);
            p.z = __expf(s[r][2] - mn);
            p.w = __expf(s[r][3] - mn);
            float rs = p.x + p.y + p.z + p.w;
            rs += __shfl_xor_sync(0xffffffffu, rs, 1);
            rs += __shfl_xor_sync(0xffffffffu, rs, 2);
            rs += __shfl_xor_sync(0xffffffffu, rs, 4);
            rs += __shfl_xor_sync(0xffffffffu, rs, 8);

            l_i[r] = l_i[r] * alpha + rs;
            *(float4*)&Ps[rl * 64 + tx * 4] = p;
#pragma unroll
            for (int dc = 0; dc < 4; dc++) o[r][dc] *= alpha;
        }
        __syncthreads();

        // ---- O += P V ----
#pragma unroll 4
        for (int j4 = 0; j4 < 16; j4++) {
            float4 v0 = *(const float4*)&Vs[(4 * j4 + 0) * 64 + tx * 4];
            float4 v1 = *(const float4*)&Vs[(4 * j4 + 1) * 64 + tx * 4];
            float4 v2 = *(const float4*)&Vs[(4 * j4 + 2) * 64 + tx * 4];
            float4 v3 = *(const float4*)&Vs[(4 * j4 + 3) * 64 + tx * 4];
#pragma unroll
            for (int r = 0; r < 8; r++) {
                int rl = ((r >> 2) * 64) + ty * 4 + (r & 3);
                float4 p = *(const float4*)&Ps[rl * 64 + 4 * j4];
                o[r][0] += p.x * v0.x + p.y * v1.x + p.z * v2.x + p.w * v3.x;
                o[r][1] += p.x * v0.y + p.y * v1.y + p.z * v2.y + p.w * v3.y;
                o[r][2] += p.x * v0.z + p.y * v1.z + p.z * v2.z + p.w * v3.z;
                o[r][3] += p.x * v0.w + p.y * v1.w + p.z * v2.w + p.w * v3.w;
            }
        }
        __syncthreads();
    }

    // ---- normalize + write [b, row, h*64 + tx*4 .. +3] ----
#pragma unroll
    for (int r = 0; r < 8; r++) {
        int rl  = ((r >> 2) * 64) + ty * 4 + (r & 3);
        int row = q0 + rl;
        float inv = 1.0f / l_i[r];
        float4 ov;
        ov.x = o[r][0] * inv;
        ov.y = o[r][1] * inv;
        ov.z = o[r][2] * inv;
        ov.w = o[r][3] * inv;
        *(float4*)&out[((size_t)b * SEQ + row) * HIDDEN + h * HEAD + tx * 4] = ov;
    }
}

// ---------------------------------------------------------------------------
extern "C" void kernel_launch(void* const* d_in, const int* in_sizes, int n_in,
                              void* d_out, int out_size)
{
    const float* x     = (const float*)d_in[0];
    const float* W_qkv = (const float*)d_in[1];
    const float* b_qkv = (const float*)d_in[2];
    const float* W_out = (const float*)d_in[3];
    const float* b_out = (const float*)d_in[4];
    float* out = (float*)d_out;

    float *qkv, *att;
    cudaGetSymbolAddress((void**)&qkv, g_qkv);
    cudaGetSymbolAddress((void**)&att, g_att);

    const int ATTN_SMEM = (64 * 128 + 64 * 64 + 64 * 64 + 128 * 64) * 4;  // 96 KB
    cudaFuncSetAttribute(attn_kernel,
                         cudaFuncAttributeMaxDynamicSharedMemorySize, ATTN_SMEM);

    // 1) qkv = x @ W_qkv + b_qkv       [4096 x 2304]
    gemm_bias<<<dim3(QKV_N / 128, M_TOT / 128), 256>>>(
        x, W_qkv, b_qkv, qkv, M_TOT, QKV_N, HIDDEN);

    // 2) causal flash attention        [4096 x 768]
    attn_kernel<<<dim3(SEQ / 128, NH, BATCH), 256, ATTN_SMEM>>>(qkv, att);

    // 3) out = att @ W_out + b_out     [4096 x 768]
    gemm_bias<<<dim3(HIDDEN / 128, M_TOT / 128), 256>>>(
        att, W_out, b_out, out, M_TOT, HIDDEN, HIDDEN);
}

// round 2
// speedup vs baseline: 2.5858x; 2.5858x over previous
#include <cuda_runtime.h>
#include <math.h>

#define HIDDEN 768
#define NH     12
#define HEAD   64
#define BATCH  2
#define SEQ    2048
#define M_TOT  (BATCH * SEQ)     // 4096
#define QKV_N  (3 * HIDDEN)      // 2304

// Scratch (allocation-free rule: __device__ globals)
__device__ float g_qkv[(size_t)M_TOT * QKV_N];   // [4096][2304]
__device__ float g_att[(size_t)M_TOT * HIDDEN];  // [4096][768]

// ---------------------------------------------------------------------------
// helpers
// ---------------------------------------------------------------------------
__device__ __forceinline__ unsigned f2tf(float x) {
    unsigned r;
    asm("cvt.rna.tf32.f32 %0, %1;" : "=r"(r) : "f"(x));
    return r;
}

// D = A(16x8) * B(8x8) + D, tf32 in, f32 accum.
// a0=(g,t) a1=(g+8,t) a2=(g,t+4) a3=(g+8,t+4); b0=(t,g) b1=(t+4,g);
// c0=(g,2t) c1=(g,2t+1) c2=(g+8,2t) c3=(g+8,2t+1)   [g=lane>>2, t=lane&3]
__device__ __forceinline__ void mma8(float* c, const unsigned* a, const unsigned* b) {
    asm volatile(
        "mma.sync.aligned.m16n8k8.row.col.f32.tf32.tf32.f32 "
        "{%0,%1,%2,%3}, {%4,%5,%6,%7}, {%8,%9}, {%0,%1,%2,%3};"
        : "+f"(c[0]), "+f"(c[1]), "+f"(c[2]), "+f"(c[3])
        : "r"(a[0]), "r"(a[1]), "r"(a[2]), "r"(a[3]), "r"(b[0]), "r"(b[1]));
}

// ---------------------------------------------------------------------------
// tf32 GEMM with bias: C[M][N] = A[M][K] @ B[K][N] + bias[N]
// BM=BN=128, BK=32, 256 threads (8 warps as 4m x 2n, warp tile 32m x 64n)
// ---------------------------------------------------------------------------
__global__ __launch_bounds__(256, 2)
void gemm_tf32(const float* __restrict__ A, const float* __restrict__ Bm,
               const float* __restrict__ bias, float* __restrict__ C,
               int M, int Nn, int K)
{
    __shared__ unsigned As[128][36];   // [m][k], pad 4 -> conflict-free both ways
    __shared__ unsigned Bs[32][136];   // [k][n], pad 8 -> conflict-free both ways

    const int tid  = threadIdx.x;
    const int lane = tid & 31;
    const int g    = lane >> 2;
    const int t    = lane & 3;
    const int warp = tid >> 5;
    const int wm0  = (warp >> 1) * 32;
    const int wn0  = (warp & 1) * 64;
    const int m0   = blockIdx.y * 128;
    const int n0   = blockIdx.x * 128;

    float acc[2][8][4];
#pragma unroll
    for (int i = 0; i < 2; i++)
#pragma unroll
        for (int j = 0; j < 8; j++)
#pragma unroll
            for (int r = 0; r < 4; r++) acc[i][j][r] = 0.f;

    for (int k0g = 0; k0g < K; k0g += 32) {
        // gmem loads (coalesced float4) into regs first — overlap prior compute
        float4 av[4], bv[4];
#pragma unroll
        for (int it = 0; it < 4; it++) {
            int f = tid + 256 * it;
            int m = f >> 3, k4 = (f & 7) << 2;
            av[it] = *(const float4*)&A[(size_t)(m0 + m) * K + k0g + k4];
            int kk = f >> 5, n4 = (f & 31) << 2;
            bv[it] = *(const float4*)&Bm[(size_t)(k0g + kk) * Nn + n0 + n4];
        }
        __syncthreads();   // prior iter's readers done
#pragma unroll
        for (int it = 0; it < 4; it++) {
            int f = tid + 256 * it;
            int m = f >> 3, k4 = (f & 7) << 2;
            uint4 ua = make_uint4(f2tf(av[it].x), f2tf(av[it].y),
                                  f2tf(av[it].z), f2tf(av[it].w));
            *(uint4*)&As[m][k4] = ua;
            int kk = f >> 5, n4 = (f & 31) << 2;
            uint4 ub = make_uint4(f2tf(bv[it].x), f2tf(bv[it].y),
                                  f2tf(bv[it].z), f2tf(bv[it].w));
            *(uint4*)&Bs[kk][n4] = ub;
        }
        __syncthreads();

#pragma unroll
        for (int ks = 0; ks < 4; ks++) {
            const int k0 = ks * 8;
            unsigned a[2][4];
#pragma unroll
            for (int am = 0; am < 2; am++) {
                int r = wm0 + am * 16 + g;
                a[am][0] = As[r][k0 + t];
                a[am][1] = As[r + 8][k0 + t];
                a[am][2] = As[r][k0 + t + 4];
                a[am][3] = As[r + 8][k0 + t + 4];
            }
            unsigned b[8][2];
#pragma unroll
            for (int an = 0; an < 8; an++) {
                int n = wn0 + an * 8 + g;
                b[an][0] = Bs[k0 + t][n];
                b[an][1] = Bs[k0 + t + 4][n];
            }
#pragma unroll
            for (int am = 0; am < 2; am++)
#pragma unroll
                for (int an = 0; an < 8; an++)
                    mma8(acc[am][an], a[am], b[an]);
        }
        __syncthreads();
    }

    // epilogue: c0,c1 -> (row, col..col+1); c2,c3 -> (row+8, ...)
#pragma unroll
    for (int am = 0; am < 2; am++) {
        int row = m0 + wm0 + am * 16 + g;
#pragma unroll
        for (int an = 0; an < 8; an++) {
            int col = n0 + wn0 + an * 8 + 2 * t;
            float2 bv = *(const float2*)&bias[col];
            float2 o0 = make_float2(acc[am][an][0] + bv.x, acc[am][an][1] + bv.y);
            float2 o1 = make_float2(acc[am][an][2] + bv.x, acc[am][an][3] + bv.y);
            *(float2*)&C[(size_t)row * Nn + col]       = o0;
            *(float2*)&C[(size_t)(row + 8) * Nn + col] = o1;
        }
    }
}

// ---------------------------------------------------------------------------
// Flash attention (causal) with tf32 mma.
// Block: 128 q-rows x one head, 256 threads = 8 warps, warp = 16 q-rows.
// kv tiles of 64. S warp tile 16x64 (8 n-atoms), PV warp tile 16x64 d.
// ---------------------------------------------------------------------------
__global__ __launch_bounds__(256, 2)
void attn_tf32(const float* __restrict__ qkv, float* __restrict__ out)
{
    extern __shared__ unsigned sm[];
    unsigned* Qs = sm;                    // [128][68]
    unsigned* Ks = Qs + 128 * 68;         // [64][72]  (d-major)
    unsigned* Vs = Ks + 64 * 72;          // [64][72]  (kv-major)
    unsigned* Ps = Vs + 64 * 72;          // [128][68]

    const int tid  = threadIdx.x;
    const int lane = tid & 31;
    const int g    = lane >> 2;
    const int t    = lane & 3;
    const int warp = tid >> 5;
    const int wm0  = warp * 16;
    const int qt   = 15 - (int)blockIdx.x;   // heavy tiles first
    const int h    = blockIdx.y;
    const int b    = blockIdx.z;
    const int q0   = qt * 128;

    const size_t base = (size_t)b * SEQ * QKV_N;
    const int qoff = h * HEAD;
    const int koff = HIDDEN + h * HEAD;
    const int voff = 2 * HIDDEN + h * HEAD;

    // Q tile -> Qs[m][d], pre-scaled by 1/sqrt(64), tf32
#pragma unroll
    for (int it = 0; it < 8; it++) {
        int f = tid + 256 * it;        // 2048 float4
        int m = f >> 4, d = (f & 15) << 2;
        float4 q = *(const float4*)&qkv[base + (size_t)(q0 + m) * QKV_N + qoff + d];
        uint4 u = make_uint4(f2tf(q.x * 0.125f), f2tf(q.y * 0.125f),
                             f2tf(q.z * 0.125f), f2tf(q.w * 0.125f));
        *(uint4*)&Qs[m * 68 + d] = u;
    }

    float o[8][4];
    float mr0 = -1e30f, mr1 = -1e30f, l0 = 0.f, l1 = 0.f;
#pragma unroll
    for (int an = 0; an < 8; an++)
#pragma unroll
        for (int r = 0; r < 4; r++) o[an][r] = 0.f;

    __syncthreads();

    const int ktiles = 2 * qt + 2;
    for (int kt = 0; kt < ktiles; kt++) {
        const int n0k = kt * 64;

        // K tile transposed -> Ks[d][j]
#pragma unroll
        for (int it = 0; it < 4; it++) {
            int f = tid + 256 * it;    // 1024 float4
            int j = f & 63, d4 = (f >> 6) << 2;
            float4 kv = *(const float4*)&qkv[base + (size_t)(n0k + j) * QKV_N + koff + d4];
            Ks[(d4 + 0) * 72 + j] = f2tf(kv.x);
            Ks[(d4 + 1) * 72 + j] = f2tf(kv.y);
            Ks[(d4 + 2) * 72 + j] = f2tf(kv.z);
            Ks[(d4 + 3) * 72 + j] = f2tf(kv.w);
        }
        // V tile natural -> Vs[j][d]
#pragma unroll
        for (int it = 0; it < 4; it++) {
            int f = tid + 256 * it;
            int j = f >> 4, d = (f & 15) << 2;
            float4 vv = *(const float4*)&qkv[base + (size_t)(n0k + j) * QKV_N + voff + d];
            uint4 u = make_uint4(f2tf(vv.x), f2tf(vv.y), f2tf(vv.z), f2tf(vv.w));
            *(uint4*)&Vs[j * 72 + d] = u;
        }
        __syncthreads();

        // ---- S = Q K^T (warp rows wm0..wm0+15, cols 0..63) ----
        float s[8][4];
#pragma unroll
        for (int an = 0; an < 8; an++)
#pragma unroll
            for (int r = 0; r < 4; r++) s[an][r] = 0.f;

#pragma unroll
        for (int ks = 0; ks < 8; ks++) {
            const int k0 = ks * 8;
            unsigned a[4];
            a[0] = Qs[(wm0 + g) * 68 + k0 + t];
            a[1] = Qs[(wm0 + g + 8) * 68 + k0 + t];
            a[2] = Qs[(wm0 + g) * 68 + k0 + t + 4];
            a[3] = Qs[(wm0 + g + 8) * 68 + k0 + t + 4];
#pragma unroll
            for (int an = 0; an < 8; an++) {
                unsigned bb[2];
                bb[0] = Ks[(k0 + t) * 72 + an * 8 + g];
                bb[1] = Ks[(k0 + t + 4) * 72 + an * 8 + g];
                mma8(s[an], a, bb);
            }
        }

        // ---- online softmax (rows r0 = q0+wm0+g, r1 = r0+8) ----
        const int r0 = q0 + wm0 + g;
        const int r1 = r0 + 8;
        if (n0k + 63 > q0 + wm0) {     // diagonal tile: apply causal mask
#pragma unroll
            for (int an = 0; an < 8; an++) {
                int c0 = n0k + an * 8 + 2 * t;
                if (c0 > r0)     s[an][0] = -1e30f;
                if (c0 + 1 > r0) s[an][1] = -1e30f;
                if (c0 > r1)     s[an][2] = -1e30f;
                if (c0 + 1 > r1) s[an][3] = -1e30f;
            }
        }
        float mx0 = -1e30f, mx1 = -1e30f;
#pragma unroll
        for (int an = 0; an < 8; an++) {
            mx0 = fmaxf(mx0, fmaxf(s[an][0], s[an][1]));
            mx1 = fmaxf(mx1, fmaxf(s[an][2], s[an][3]));
        }
        mx0 = fmaxf(mx0, __shfl_xor_sync(0xffffffffu, mx0, 1));
        mx0 = fmaxf(mx0, __shfl_xor_sync(0xffffffffu, mx0, 2));
        mx1 = fmaxf(mx1, __shfl_xor_sync(0xffffffffu, mx1, 1));
        mx1 = fmaxf(mx1, __shfl_xor_sync(0xffffffffu, mx1, 2));

        float mn0 = fmaxf(mr0, mx0), mn1 = fmaxf(mr1, mx1);
        float al0 = __expf(mr0 - mn0), al1 = __expf(mr1 - mn1);
        mr0 = mn0; mr1 = mn1;

        float rs0 = 0.f, rs1 = 0.f;
#pragma unroll
        for (int an = 0; an < 8; an++) {
            float p00 = __expf(s[an][0] - mn0);
            float p01 = __expf(s[an][1] - mn0);
            float p10 = __expf(s[an][2] - mn1);
            float p11 = __expf(s[an][3] - mn1);
            rs0 += p00 + p01;
            rs1 += p10 + p11;
            uint2 u0 = make_uint2(f2tf(p00), f2tf(p01));
            uint2 u1 = make_uint2(f2tf(p10), f2tf(p11));
            *(uint2*)&Ps[(wm0 + g) * 68 + an * 8 + 2 * t]     = u0;
            *(uint2*)&Ps[(wm0 + g + 8) * 68 + an * 8 + 2 * t] = u1;
#pragma unroll
            for (int r = 0; r < 2; r++) { o[an][r] *= al0; o[an][r + 2] *= al1; }
        }
        rs0 += __shfl_xor_sync(0xffffffffu, rs0, 1);
        rs0 += __shfl_xor_sync(0xffffffffu, rs0, 2);
        rs1 += __shfl_xor_sync(0xffffffffu, rs1, 1);
        rs1 += __shfl_xor_sync(0xffffffffu, rs1, 2);
        l0 = l0 * al0 + rs0;
        l1 = l1 * al1 + rs1;

        __syncthreads();   // Ps visible to own warp's A-frag loads is trivial,
                           // but Ks/Vs must not be overwritten while others read;
                           // also orders Ps (none cross-warp) cheaply.

        // ---- O += P V ----
#pragma unroll
        for (int ks = 0; ks < 8; ks++) {
            const int kv0 = ks * 8;
            unsigned a[4];
            a[0] = Ps[(wm0 + g) * 68 + kv0 + t];
            a[1] = Ps[(wm0 + g + 8) * 68 + kv0 + t];
            a[2] = Ps[(wm0 + g) * 68 + kv0 + t + 4];
            a[3] = Ps[(wm0 + g + 8) * 68 + kv0 + t + 4];
#pragma unroll
            for (int an = 0; an < 8; an++) {
                unsigned bb[2];
                bb[0] = Vs[(kv0 + t) * 72 + an * 8 + g];
                bb[1] = Vs[(kv0 + t + 4) * 72 + an * 8 + g];
                mma8(o[an], a, bb);
            }
        }
        __syncthreads();   // all warps done with Ks/Vs/Ps before next tile
    }

    // ---- normalize + write ----
    const float inv0 = 1.0f / l0, inv1 = 1.0f / l1;
    const int r0 = q0 + wm0 + g;
#pragma unroll
    for (int an = 0; an < 8; an++) {
        int col = h * HEAD + an * 8 + 2 * t;
        float2 w0 = make_float2(o[an][0] * inv0, o[an][1] * inv0);
        float2 w1 = make_float2(o[an][2] * inv1, o[an][3] * inv1);
        *(float2*)&out[((size_t)b * SEQ + r0) * HIDDEN + col]     = w0;
        *(float2*)&out[((size_t)b * SEQ + r0 + 8) * HIDDEN + col] = w1;
    }
}

// ---------------------------------------------------------------------------
extern "C" void kernel_launch(void* const* d_in, const int* in_sizes, int n_in,
                              void* d_out, int out_size)
{
    const float* x     = (const float*)d_in[0];
    const float* W_qkv = (const float*)d_in[1];
    const float* b_qkv = (const float*)d_in[2];
    const float* W_out = (const float*)d_in[3];
    const float* b_out = (const float*)d_in[4];
    float* out = (float*)d_out;

    float *qkv, *att;
    cudaGetSymbolAddress((void**)&qkv, g_qkv);
    cudaGetSymbolAddress((void**)&att, g_att);

    const int ATTN_SMEM = (128 * 68 + 64 * 72 + 64 * 72 + 128 * 68) * 4;  // 106496 B
    cudaFuncSetAttribute(attn_tf32,
                         cudaFuncAttributeMaxDynamicSharedMemorySize, ATTN_SMEM);

    // 1) qkv = x @ W_qkv + b_qkv       [4096 x 2304]
    gemm_tf32<<<dim3(QKV_N / 128, M_TOT / 128), 256>>>(
        x, W_qkv, b_qkv, qkv, M_TOT, QKV_N, HIDDEN);

    // 2) causal flash attention        [4096 x 768]
    attn_tf32<<<dim3(SEQ / 128, NH, BATCH), 256, ATTN_SMEM>>>(qkv, att);

    // 3) out = att @ W_out + b_out     [4096 x 768]
    gemm_tf32<<<dim3(HIDDEN / 128, M_TOT / 128), 256>>>(
        att, W_out, b_out, out, M_TOT, HIDDEN, HIDDEN);
}

// round 3
// speedup vs baseline: 2.7006x; 1.0444x over previous
#include <cuda_runtime.h>
#include <math.h>

#define HIDDEN 768
#define NH     12
#define HEAD   64
#define BATCH  2
#define SEQ    2048
#define M_TOT  (BATCH * SEQ)     // 4096
#define QKV_N  (3 * HIDDEN)      // 2304

// Scratch (allocation-free rule: __device__ globals)
__device__ float g_qkv[(size_t)M_TOT * QKV_N];   // [4096][2304]
__device__ float g_att[(size_t)M_TOT * HIDDEN];  // [4096][768]

// ---------------------------------------------------------------------------
// helpers
// ---------------------------------------------------------------------------
__device__ __forceinline__ unsigned f2tf(float x) {
    unsigned r;
    asm("cvt.rna.tf32.f32 %0, %1;" : "=r"(r) : "f"(x));
    return r;
}
__device__ __forceinline__ uint4 cvt4(float4 v) {
    return make_uint4(f2tf(v.x), f2tf(v.y), f2tf(v.z), f2tf(v.w));
}

// D = A(16x8) * B(8x8) + D, tf32 in, f32 accum.
// a0=(g,t) a1=(g+8,t) a2=(g,t+4) a3=(g+8,t+4); b0=(t,g) b1=(t+4,g);
// c0=(g,2t) c1=(g,2t+1) c2=(g+8,2t) c3=(g+8,2t+1)   [g=lane>>2, t=lane&3]
__device__ __forceinline__ void mma8(float* c, const unsigned* a, unsigned b0, unsigned b1) {
    asm volatile(
        "mma.sync.aligned.m16n8k8.row.col.f32.tf32.tf32.f32 "
        "{%0,%1,%2,%3}, {%4,%5,%6,%7}, {%8,%9}, {%0,%1,%2,%3};"
        : "+f"(c[0]), "+f"(c[1]), "+f"(c[2]), "+f"(c[3])
        : "r"(a[0]), "r"(a[1]), "r"(a[2]), "r"(a[3]), "r"(b0), "r"(b1));
}

// ldmatrix x4 (b16 view): on a 16x8 b32 tile at (r0,c0), row stride S words:
// lane addr row = r0 + (lane&7) + (lane&8), col = c0 + ((lane>>4)<<2)
// regs: q0=(g, t) q1=(g+8, t) q2=(g, t+4) q3=(g+8, t+4)
__device__ __forceinline__ void ldsm4(unsigned& r0, unsigned& r1, unsigned& r2,
                                      unsigned& r3, unsigned saddr) {
    asm volatile("ldmatrix.sync.aligned.m8n8.x4.shared.b16 {%0,%1,%2,%3}, [%4];"
                 : "=r"(r0), "=r"(r1), "=r"(r2), "=r"(r3) : "r"(saddr));
}

// ---------------------------------------------------------------------------
// tf32 GEMM with bias: C[M][N] = A[M][K] @ B[K][N] + bias[N]
// BM=BN=128, BK=32, 512 threads (16 warps as 4m x 4n, warp tile 32m x 32n).
// Double-buffered smem, 1 barrier per k-tile, LDG prefetch spans mma phase.
// ---------------------------------------------------------------------------
#define GEMM_SMEM ((2 * 128 * 36 + 2 * 32 * 136) * 4)   // 71680 B

__global__ __launch_bounds__(512, 1)
void gemm_tf32(const float* __restrict__ A, const float* __restrict__ Bm,
               const float* __restrict__ bias, float* __restrict__ C,
               int M, int Nn, int K)
{
    extern __shared__ unsigned gsm[];
    unsigned* As = gsm;                    // [2][128][36]
    unsigned* Bs = gsm + 2 * 128 * 36;     // [2][32][136]

    const int tid  = threadIdx.x;
    const int lane = tid & 31;
    const int g    = lane >> 2;
    const int t    = lane & 3;
    const int warp = tid >> 5;
    const int wm0  = (warp >> 2) * 32;
    const int wn0  = (warp & 3) * 32;
    const int m0   = blockIdx.y * 128;
    const int n0   = blockIdx.x * 128;

    // staging maps (verified conflict-free per STS.128 phase, coalesced LDG)
    const int am_r = tid >> 2;            // 0..127
    const int ak   = (tid & 3) << 3;      // 0,8,16,24
    const int bk   = tid >> 4;            // 0..31
    const int bn   = (tid & 15) << 2;     // 0..60

    const float* Ap = A + (size_t)(m0 + am_r) * K + ak;
    const float* Bp = Bm + (size_t)bk * Nn + n0 + bn;

    // ldmatrix lane geometry
    const int arow = (lane & 7) + (lane & 8);
    const int acol = (lane >> 4) << 2;
    const unsigned aBase = (unsigned)__cvta_generic_to_shared(As);
    const unsigned bBase = (unsigned)__cvta_generic_to_shared(Bs);

    float4 a0v = *(const float4*)Ap;
    float4 a1v = *(const float4*)(Ap + 4);
    float4 b0v = *(const float4*)Bp;
    float4 b1v = *(const float4*)(Bp + 64);

    float acc[2][4][4];
#pragma unroll
    for (int i = 0; i < 2; i++)
#pragma unroll
        for (int j = 0; j < 4; j++)
#pragma unroll
            for (int r = 0; r < 4; r++) acc[i][j][r] = 0.f;

    // prologue: stage tile 0 into buf 0
    *(uint4*)&As[(size_t)am_r * 36 + ak]     = cvt4(a0v);
    *(uint4*)&As[(size_t)am_r * 36 + ak + 4] = cvt4(a1v);
    *(uint4*)&Bs[(size_t)bk * 136 + bn]      = cvt4(b0v);
    *(uint4*)&Bs[(size_t)bk * 136 + bn + 64] = cvt4(b1v);
    __syncthreads();

    const int nk = K >> 5;
    for (int kt = 0; kt < nk; kt++) {
        const int st = kt & 1;
        const bool more = (kt + 1 < nk);
        if (more) {
            Ap += 32;
            Bp += (size_t)32 * Nn;
            a0v = *(const float4*)Ap;
            a1v = *(const float4*)(Ap + 4);
            b0v = *(const float4*)Bp;
            b1v = *(const float4*)(Bp + 64);
        }

        const unsigned aS = aBase + (unsigned)((st * 128 + wm0 + arow) * 36 + acol) * 4;
        const unsigned bRow = (unsigned)(st * 32) * 136;

#pragma unroll
        for (int ks = 0; ks < 4; ks++) {
            const int k0 = ks * 8;
            unsigned a[2][4];
            ldsm4(a[0][0], a[0][1], a[0][2], a[0][3], aS + (unsigned)k0 * 4);
            ldsm4(a[1][0], a[1][1], a[1][2], a[1][3], aS + (unsigned)(16 * 36 + k0) * 4);
            unsigned bf[4][2];
#pragma unroll
            for (int an = 0; an < 4; an++) {
                bf[an][0] = Bs[bRow + (unsigned)(k0 + t) * 136 + wn0 + an * 8 + g];
                bf[an][1] = Bs[bRow + (unsigned)(k0 + t + 4) * 136 + wn0 + an * 8 + g];
            }
#pragma unroll
            for (int am = 0; am < 2; am++)
#pragma unroll
                for (int an = 0; an < 4; an++)
                    mma8(acc[am][an], a[am], bf[an][0], bf[an][1]);
        }

        if (more) {
            const int s2 = st ^ 1;
            *(uint4*)&As[(size_t)(s2 * 128 + am_r) * 36 + ak]     = cvt4(a0v);
            *(uint4*)&As[(size_t)(s2 * 128 + am_r) * 36 + ak + 4] = cvt4(a1v);
            *(uint4*)&Bs[(size_t)(s2 * 32 + bk) * 136 + bn]       = cvt4(b0v);
            *(uint4*)&Bs[(size_t)(s2 * 32 + bk) * 136 + bn + 64]  = cvt4(b1v);
        }
        __syncthreads();
    }

    // epilogue with bias
#pragma unroll
    for (int am = 0; am < 2; am++) {
        int row = m0 + wm0 + am * 16 + g;
#pragma unroll
        for (int an = 0; an < 4; an++) {
            int col = n0 + wn0 + an * 8 + 2 * t;
            float2 bv = *(const float2*)&bias[col];
            float2 o0 = make_float2(acc[am][an][0] + bv.x, acc[am][an][1] + bv.y);
            float2 o1 = make_float2(acc[am][an][2] + bv.x, acc[am][an][3] + bv.y);
            *(float2*)&C[(size_t)row * Nn + col]       = o0;
            *(float2*)&C[(size_t)(row + 8) * Nn + col] = o1;
        }
    }
}

// ---------------------------------------------------------------------------
// Flash attention (causal), tf32 mma, 256 threads = 8 warps, 128 q-rows/block.
// K/V prefetched to registers one tile ahead; ldmatrix for Q/K/P fragments.
// Smem: Qs[128][68], Ks[64][68] (row-major), Vs[64][72], Ps[128][68].
// ---------------------------------------------------------------------------
#define ATTN_SMEM ((128 * 68 + 64 * 68 + 64 * 72 + 128 * 68) * 4)   // 105472 B

__global__ __launch_bounds__(256, 2)
void attn_tf32(const float* __restrict__ qkv, float* __restrict__ out)
{
    extern __shared__ unsigned sm[];
    unsigned* Qs = sm;                    // [128][68]
    unsigned* Ks = Qs + 128 * 68;         // [64][68]  row-major [j][d]
    unsigned* Vs = Ks + 64 * 68;          // [64][72]  row-major [j][d]
    unsigned* Ps = Vs + 64 * 72;          // [128][68]

    const int tid  = threadIdx.x;
    const int lane = tid & 31;
    const int g    = lane >> 2;
    const int t    = lane & 3;
    const int warp = tid >> 5;
    const int wm0  = warp * 16;
    const int qt   = 15 - (int)blockIdx.x;   // heavy tiles first
    const int h    = blockIdx.y;
    const int b    = blockIdx.z;
    const int q0   = qt * 128;

    const size_t base = (size_t)b * SEQ * QKV_N;
    const int qoff = h * HEAD;
    const int koff = HIDDEN + h * HEAD;
    const int voff = 2 * HIDDEN + h * HEAD;

    // ldmatrix lane geometry
    const int arow = (lane & 7) + (lane & 8);
    const int acol = (lane >> 4) << 2;
    const unsigned qBase = (unsigned)__cvta_generic_to_shared(Qs)
                         + (unsigned)((wm0 + arow) * 68 + acol) * 4;
    const unsigned kBase = (unsigned)__cvta_generic_to_shared(Ks)
                         + (unsigned)(arow * 68 + acol) * 4;
    const unsigned pBase = (unsigned)__cvta_generic_to_shared(Ps)
                         + (unsigned)((wm0 + arow) * 68 + acol) * 4;

    // staging maps
    const int sj = tid >> 4;              // 0..15 (row block)
    const int sd = (tid & 15) << 2;       // 0..60

    // Q tile -> Qs[m][d], pre-scaled by 1/sqrt(64)
#pragma unroll
    for (int it = 0; it < 8; it++) {
        int m = sj + 16 * it;
        float4 q = *(const float4*)&qkv[base + (size_t)(q0 + m) * QKV_N + qoff + sd];
        uint4 u = make_uint4(f2tf(q.x * 0.125f), f2tf(q.y * 0.125f),
                             f2tf(q.z * 0.125f), f2tf(q.w * 0.125f));
        *(uint4*)&Qs[m * 68 + sd] = u;
    }

    // prefetch K/V tile 0
    float4 kr[4], vr[4];
#pragma unroll
    for (int it = 0; it < 4; it++) {
        int j = sj + 16 * it;
        kr[it] = *(const float4*)&qkv[base + (size_t)j * QKV_N + koff + sd];
        vr[it] = *(const float4*)&qkv[base + (size_t)j * QKV_N + voff + sd];
    }

    float o[8][4];
    float mr0 = -1e30f, mr1 = -1e30f, l0 = 0.f, l1 = 0.f;
#pragma unroll
    for (int an = 0; an < 8; an++)
#pragma unroll
        for (int r = 0; r < 4; r++) o[an][r] = 0.f;

    __syncthreads();   // Q visible

    const int ktiles = 2 * qt + 2;
    for (int kt = 0; kt < ktiles; kt++) {
        const int n0k = kt * 64;

        // stage K/V from prefetch regs (prev readers done via end-of-iter barrier)
#pragma unroll
        for (int it = 0; it < 4; it++) {
            int j = sj + 16 * it;
            *(uint4*)&Ks[j * 68 + sd] = cvt4(kr[it]);
            *(uint4*)&Vs[j * 72 + sd] = cvt4(vr[it]);
        }
        __syncthreads();

        if (kt + 1 < ktiles) {   // prefetch next tile; latency hidden below
            const size_t roff = base + (size_t)(n0k + 64) * QKV_N;
#pragma unroll
            for (int it = 0; it < 4; it++) {
                int j = sj + 16 * it;
                kr[it] = *(const float4*)&qkv[roff + (size_t)j * QKV_N + koff + sd];
                vr[it] = *(const float4*)&qkv[roff + (size_t)j * QKV_N + voff + sd];
            }
        }

        if (n0k <= q0 + wm0 + 15) {   // skip fully-masked tiles (barriers still hit)
            // ---- S = Q K^T ----
            float s[8][4];
#pragma unroll
            for (int an = 0; an < 8; an++)
#pragma unroll
                for (int r = 0; r < 4; r++) s[an][r] = 0.f;

#pragma unroll
            for (int ks = 0; ks < 8; ks++) {
                const unsigned kofs = (unsigned)(ks * 8) * 4;
                unsigned a[4];
                ldsm4(a[0], a[1], a[2], a[3], qBase + kofs);
#pragma unroll
                for (int p = 0; p < 4; p++) {
                    unsigned q0r, q1r, q2r, q3r;   // b-frags for an=2p, 2p+1
                    ldsm4(q0r, q1r, q2r, q3r,
                          kBase + (unsigned)(p * 16 * 68) * 4 + kofs);
                    mma8(s[2 * p],     a, q0r, q2r);
                    mma8(s[2 * p + 1], a, q1r, q3r);
                }
            }

            // ---- online softmax (rows r0 = q0+wm0+g, r1 = r0+8) ----
            const int r0 = q0 + wm0 + g;
            const int r1 = r0 + 8;
            if (n0k + 63 > q0 + wm0) {   // diagonal tile: causal mask
#pragma unroll
                for (int an = 0; an < 8; an++) {
                    int c0 = n0k + an * 8 + 2 * t;
                    if (c0 > r0)     s[an][0] = -1e30f;
                    if (c0 + 1 > r0) s[an][1] = -1e30f;
                    if (c0 > r1)     s[an][2] = -1e30f;
                    if (c0 + 1 > r1) s[an][3] = -1e30f;
                }
            }
            float mx0 = -1e30f, mx1 = -1e30f;
#pragma unroll
            for (int an = 0; an < 8; an++) {
                mx0 = fmaxf(mx0, fmaxf(s[an][0], s[an][1]));
                mx1 = fmaxf(mx1, fmaxf(s[an][2], s[an][3]));
            }
            mx0 = fmaxf(mx0, __shfl_xor_sync(0xffffffffu, mx0, 1));
            mx0 = fmaxf(mx0, __shfl_xor_sync(0xffffffffu, mx0, 2));
            mx1 = fmaxf(mx1, __shfl_xor_sync(0xffffffffu, mx1, 1));
            mx1 = fmaxf(mx1, __shfl_xor_sync(0xffffffffu, mx1, 2));

            float mn0 = fmaxf(mr0, mx0), mn1 = fmaxf(mr1, mx1);
            float al0 = __expf(mr0 - mn0), al1 = __expf(mr1 - mn1);
            mr0 = mn0; mr1 = mn1;

            float rs0 = 0.f, rs1 = 0.f;
#pragma unroll
            for (int an = 0; an < 8; an++) {
                float p00 = __expf(s[an][0] - mn0);
                float p01 = __expf(s[an][1] - mn0);
                float p10 = __expf(s[an][2] - mn1);
                float p11 = __expf(s[an][3] - mn1);
                rs0 += p00 + p01;
                rs1 += p10 + p11;
                *(uint2*)&Ps[(wm0 + g) * 68 + an * 8 + 2 * t] =
                    make_uint2(f2tf(p00), f2tf(p01));
                *(uint2*)&Ps[(wm0 + g + 8) * 68 + an * 8 + 2 * t] =
                    make_uint2(f2tf(p10), f2tf(p11));
#pragma unroll
                for (int r = 0; r < 2; r++) { o[an][r] *= al0; o[an][r + 2] *= al1; }
            }
            rs0 += __shfl_xor_sync(0xffffffffu, rs0, 1);
            rs0 += __shfl_xor_sync(0xffffffffu, rs0, 2);
            rs1 += __shfl_xor_sync(0xffffffffu, rs1, 1);
            rs1 += __shfl_xor_sync(0xffffffffu, rs1, 2);
            l0 = l0 * al0 + rs0;
            l1 = l1 * al1 + rs1;

            __syncwarp();   // Ps is warp-private: warp-level ordering suffices

            // ---- O += P V ----
#pragma unroll
            for (int ks = 0; ks < 8; ks++) {
                const int kv0 = ks * 8;
                unsigned a[4];
                ldsm4(a[0], a[1], a[2], a[3], pBase + (unsigned)kv0 * 4);
#pragma unroll
                for (int an = 0; an < 8; an++) {
                    unsigned b0 = Vs[(kv0 + t) * 72 + an * 8 + g];
                    unsigned b1 = Vs[(kv0 + t + 4) * 72 + an * 8 + g];
                    mma8(o[an], a, b0, b1);
                }
            }
        }
        __syncthreads();   // all readers done before next tile's STS
    }

    // ---- normalize + write ----
    const float inv0 = 1.0f / l0, inv1 = 1.0f / l1;
    const int r0 = q0 + wm0 + g;
#pragma unroll
    for (int an = 0; an < 8; an++) {
        int col = h * HEAD + an * 8 + 2 * t;
        float2 w0 = make_float2(o[an][0] * inv0, o[an][1] * inv0);
        float2 w1 = make_float2(o[an][2] * inv1, o[an][3] * inv1);
        *(float2*)&out[((size_t)b * SEQ + r0) * HIDDEN + col]     = w0;
        *(float2*)&out[((size_t)b * SEQ + r0 + 8) * HIDDEN + col] = w1;
    }
}

// ---------------------------------------------------------------------------
extern "C" void kernel_launch(void* const* d_in, const int* in_sizes, int n_in,
                              void* d_out, int out_size)
{
    const float* x     = (const float*)d_in[0];
    const float* W_qkv = (const float*)d_in[1];
    const float* b_qkv = (const float*)d_in[2];
    const float* W_out = (const float*)d_in[3];
    const float* b_out = (const float*)d_in[4];
    float* out = (float*)d_out;

    float *qkv, *att;
    cudaGetSymbolAddress((void**)&qkv, g_qkv);
    cudaGetSymbolAddress((void**)&att, g_att);

    cudaFuncSetAttribute(gemm_tf32,
                         cudaFuncAttributeMaxDynamicSharedMemorySize, GEMM_SMEM);
    cudaFuncSetAttribute(attn_tf32,
                         cudaFuncAttributeMaxDynamicSharedMemorySize, ATTN_SMEM);

    // 1) qkv = x @ W_qkv + b_qkv       [4096 x 2304]
    gemm_tf32<<<dim3(QKV_N / 128, M_TOT / 128), 512, GEMM_SMEM>>>(
        x, W_qkv, b_qkv, qkv, M_TOT, QKV_N, HIDDEN);

    // 2) causal flash attention        [4096 x 768]
    attn_tf32<<<dim3(SEQ / 128, NH, BATCH), 256, ATTN_SMEM>>>(qkv, att);

    // 3) out = att @ W_out + b_out     [4096 x 768]
    gemm_tf32<<<dim3(HIDDEN / 128, M_TOT / 128), 512, GEMM_SMEM>>>(
        att, W_out, b_out, out, M_TOT, HIDDEN, HIDDEN);
}

// round 4
// speedup vs baseline: 3.2679x; 1.2101x over previous
#include <cuda_runtime.h>
#include <math.h>

#define HIDDEN 768
#define NH     12
#define HEAD   64
#define BATCH  2
#define SEQ    2048
#define M_TOT  (BATCH * SEQ)     // 4096
#define QKV_N  (3 * HIDDEN)      // 2304

// Scratch (allocation-free rule: __device__ globals)
__device__ float g_qkv[(size_t)M_TOT * QKV_N];    // [4096][2304] tf32-rounded
__device__ float g_att[(size_t)M_TOT * HIDDEN];   // [4096][768]  tf32-rounded
__device__ float g_xr[(size_t)M_TOT * HIDDEN];    // x rounded
__device__ float g_wqkvr[(size_t)HIDDEN * QKV_N]; // W_qkv rounded
__device__ float g_woutr[(size_t)HIDDEN * HIDDEN];// W_out rounded

// ---------------------------------------------------------------------------
// helpers
// ---------------------------------------------------------------------------
__device__ __forceinline__ unsigned f2tf(float x) {
    unsigned r;
    asm("cvt.rna.tf32.f32 %0, %1;" : "=r"(r) : "f"(x));
    return r;
}
__device__ __forceinline__ void cp16(unsigned dst, const float* src) {
    asm volatile("cp.async.cg.shared.global [%0], [%1], 16;\n"
                 :: "r"(dst), "l"(src));
}
__device__ __forceinline__ void cp_commit() {
    asm volatile("cp.async.commit_group;\n" ::: "memory");
}
template <int N>
__device__ __forceinline__ void cp_wait() {
    asm volatile("cp.async.wait_group %0;\n" :: "n"(N) : "memory");
}

// D = A(16x8) * B(8x8) + D, tf32 in, f32 accum.
__device__ __forceinline__ void mma8(float* c, const unsigned* a, unsigned b0, unsigned b1) {
    asm volatile(
        "mma.sync.aligned.m16n8k8.row.col.f32.tf32.tf32.f32 "
        "{%0,%1,%2,%3}, {%4,%5,%6,%7}, {%8,%9}, {%0,%1,%2,%3};"
        : "+f"(c[0]), "+f"(c[1]), "+f"(c[2]), "+f"(c[3])
        : "r"(a[0]), "r"(a[1]), "r"(a[2]), "r"(a[3]), "r"(b0), "r"(b1));
}
__device__ __forceinline__ void ldsm4(unsigned& r0, unsigned& r1, unsigned& r2,
                                      unsigned& r3, unsigned saddr) {
    asm volatile("ldmatrix.sync.aligned.m8n8.x4.shared.b16 {%0,%1,%2,%3}, [%4];"
                 : "=r"(r0), "=r"(r1), "=r"(r2), "=r"(r3) : "r"(saddr));
}

// ---------------------------------------------------------------------------
// prepass: round f32 -> tf32 bits (element count multiple of 4)
// ---------------------------------------------------------------------------
__global__ void round_tf32(const float* __restrict__ src, float* __restrict__ dst, int n4)
{
    int i = blockIdx.x * blockDim.x + threadIdx.x;
    if (i < n4) {
        float4 v = ((const float4*)src)[i];
        uint4 u = make_uint4(f2tf(v.x), f2tf(v.y), f2tf(v.z), f2tf(v.w));
        ((uint4*)dst)[i] = u;
    }
}

// ---------------------------------------------------------------------------
// tf32 GEMM with bias: C = A @ B + bias. Inputs already tf32-rounded.
// BM=BN=128, BK=32, 256 threads (8 warps 4m x 2n, warp tile 32x64), occ 2.
// 3-stage cp.async pipeline, 1 barrier per k-tile.
// ---------------------------------------------------------------------------
#define GEMM_SMEM (3 * (128 * 36 + 32 * 136) * 4)   // 107520 B

__global__ __launch_bounds__(256, 2)
void gemm_tf32(const float* __restrict__ A, const float* __restrict__ Bm,
               const float* __restrict__ bias, float* __restrict__ C,
               int M, int Nn, int K, int round_out)
{
    extern __shared__ unsigned gsm[];
    // stage s: As at s*(128*36), Bs at 3*128*36 + s*(32*136)
    unsigned* Bs = gsm + 3 * 128 * 36;

    const int tid  = threadIdx.x;
    const int lane = tid & 31;
    const int g    = lane >> 2;
    const int t    = lane & 3;
    const int warp = tid >> 5;
    const int wm0  = (warp >> 1) * 32;
    const int wn0  = (warp & 1) * 64;
    const int m0   = blockIdx.y * 128;
    const int n0   = blockIdx.x * 128;

    // cp.async maps: A row r0+32i, kword kw fixed; B row kb0+8i, nword nw fixed
    const int ar0 = tid >> 3;              // 0..31
    const int akw = (tid & 7) << 2;        // 0,4,..,28
    const int bk0 = tid >> 5;              // 0..7
    const int bnw = (tid & 31) << 2;       // 0..124

    const float* Apt = A + (size_t)(m0 + ar0) * K + akw;
    const float* Bpt = Bm + (size_t)bk0 * Nn + n0 + bnw;

    const unsigned aBase = (unsigned)__cvta_generic_to_shared(gsm);
    const unsigned bBase = (unsigned)__cvta_generic_to_shared(Bs);

    // ldmatrix lane geometry
    const int arow = (lane & 7) + (lane & 8);
    const int acol = (lane >> 4) << 2;

    float acc[2][8][4];
#pragma unroll
    for (int i = 0; i < 2; i++)
#pragma unroll
        for (int j = 0; j < 8; j++)
#pragma unroll
            for (int r = 0; r < 4; r++) acc[i][j][r] = 0.f;

    const int nk = K >> 5;   // 24

#define GEMM_ISSUE(stage, kt)                                                  \
    {                                                                          \
        const float* ap = Apt + (size_t)(kt) * 32;                             \
        const float* bp = Bpt + (size_t)(kt) * 32 * Nn;                        \
        unsigned ad = aBase + (unsigned)(((stage) * 128 + ar0) * 36 + akw) * 4;\
        unsigned bd = bBase + (unsigned)(((stage) * 32 + bk0) * 136 + bnw) * 4;\
        _Pragma("unroll")                                                      \
        for (int i = 0; i < 4; i++) {                                          \
            cp16(ad + (unsigned)(32 * 36 * 4) * i, ap + (size_t)32 * i * K);   \
            cp16(bd + (unsigned)(8 * 136 * 4) * i, bp + (size_t)8 * i * Nn);   \
        }                                                                      \
        cp_commit();                                                           \
    }

    GEMM_ISSUE(0, 0)
    GEMM_ISSUE(1, 1)

    for (int kt = 0; kt < nk; kt++) {
        const int st = kt % 3;
        if (kt + 1 < nk) cp_wait<1>(); else cp_wait<0>();
        __syncthreads();
        if (kt + 2 < nk) {
            const int s2 = (kt + 2) % 3;
            GEMM_ISSUE(s2, kt + 2)
        }

        const unsigned aS = aBase + (unsigned)((st * 128 + wm0 + arow) * 36 + acol) * 4;
        const unsigned bRow = (unsigned)(st * 32) * 136;

#pragma unroll
        for (int ks = 0; ks < 4; ks++) {
            const int k0 = ks * 8;
            unsigned a[2][4];
            ldsm4(a[0][0], a[0][1], a[0][2], a[0][3], aS + (unsigned)k0 * 4);
            ldsm4(a[1][0], a[1][1], a[1][2], a[1][3], aS + (unsigned)(16 * 36 + k0) * 4);
            unsigned bf[8][2];
#pragma unroll
            for (int an = 0; an < 8; an++) {
                bf[an][0] = Bs[bRow + (unsigned)(k0 + t) * 136 + wn0 + an * 8 + g];
                bf[an][1] = Bs[bRow + (unsigned)(k0 + t + 4) * 136 + wn0 + an * 8 + g];
            }
#pragma unroll
            for (int am = 0; am < 2; am++)
#pragma unroll
                for (int an = 0; an < 8; an++)
                    mma8(acc[am][an], a[am], bf[an][0], bf[an][1]);
        }
        __syncthreads();   // readers done before stage st is re-filled (kt+3)
    }

    // epilogue with bias (+ optional tf32 rounding for intermediates)
#pragma unroll
    for (int am = 0; am < 2; am++) {
        int row = m0 + wm0 + am * 16 + g;
#pragma unroll
        for (int an = 0; an < 8; an++) {
            int col = n0 + wn0 + an * 8 + 2 * t;
            float2 bv = *(const float2*)&bias[col];
            float v00 = acc[am][an][0] + bv.x, v01 = acc[am][an][1] + bv.y;
            float v10 = acc[am][an][2] + bv.x, v11 = acc[am][an][3] + bv.y;
            float2 o0, o1;
            if (round_out) {
                o0 = make_float2(__uint_as_float(f2tf(v00)), __uint_as_float(f2tf(v01)));
                o1 = make_float2(__uint_as_float(f2tf(v10)), __uint_as_float(f2tf(v11)));
            } else {
                o0 = make_float2(v00, v01);
                o1 = make_float2(v10, v11);
            }
            *(float2*)&C[(size_t)row * Nn + col]       = o0;
            *(float2*)&C[(size_t)(row + 8) * Nn + col] = o1;
        }
    }
}

// ---------------------------------------------------------------------------
// Flash attention (causal), tf32 mma. 256 threads = 8 warps, 128 q-rows/block.
// Q-fragments in registers; Ps overlays Qs; K/V double-buffered via cp.async;
// ONE barrier per kv-tile.
// smem: QP[128][68] | Ks[2][64][68] | Vs[2][64][72]  = 106496 B
// ---------------------------------------------------------------------------
#define ATTN_SMEM ((128 * 68 + 2 * 64 * 68 + 2 * 64 * 72) * 4)

__global__ __launch_bounds__(256, 2)
void attn_tf32(const float* __restrict__ qkv, float* __restrict__ out)
{
    extern __shared__ unsigned sm[];
    unsigned* QP = sm;                          // [128][68] (Q then P)
    const unsigned KS_OFF = 128 * 68;           // word offsets
    const unsigned VS_OFF = KS_OFF + 2 * 64 * 68;

    const int tid  = threadIdx.x;
    const int lane = tid & 31;
    const int g    = lane >> 2;
    const int t    = lane & 3;
    const int warp = tid >> 5;
    const int wm0  = warp * 16;
    const int qt   = 15 - (int)blockIdx.x;      // heavy tiles first
    const int h    = blockIdx.y;
    const int b    = blockIdx.z;
    const int q0   = qt * 128;

    const size_t base = (size_t)b * SEQ * QKV_N;
    const int qoff = h * HEAD;
    const int koff = HIDDEN + h * HEAD;
    const int voff = 2 * HIDDEN + h * HEAD;

    const unsigned smBase = (unsigned)__cvta_generic_to_shared(sm);
    const int arow = (lane & 7) + (lane & 8);
    const int acol = (lane >> 4) << 2;
    const unsigned qpBase = smBase + (unsigned)((wm0 + arow) * 68 + acol) * 4;

    // cp.async staging map for K/V: row j = sj+16i, dword sd fixed
    const int sj = tid >> 4;                    // 0..15
    const int sd = (tid & 15) << 2;             // 0..60

#define ATTN_ISSUE(stage, n0k_)                                                 \
    {                                                                           \
        const float* kp = qkv + base + (size_t)((n0k_) + sj) * QKV_N + koff + sd;\
        const float* vp = qkv + base + (size_t)((n0k_) + sj) * QKV_N + voff + sd;\
        unsigned kd = smBase + (KS_OFF + (unsigned)((stage) * 64 + sj) * 68 + sd) * 4;\
        unsigned vd = smBase + (VS_OFF + (unsigned)((stage) * 64 + sj) * 72 + sd) * 4;\
        _Pragma("unroll")                                                       \
        for (int i = 0; i < 4; i++) {                                           \
            cp16(kd + (unsigned)(16 * 68 * 4) * i, kp + (size_t)16 * i * QKV_N);\
            cp16(vd + (unsigned)(16 * 72 * 4) * i, vp + (size_t)16 * i * QKV_N);\
        }                                                                       \
        cp_commit();                                                            \
    }

    ATTN_ISSUE(0, 0)   // start K/V tile 0 DMA before Q staging

    // Q tile -> QP[m][d], pre-scaled by 1/sqrt(64) (exact pow2 mult)
#pragma unroll
    for (int it = 0; it < 8; it++) {
        int m = sj + 16 * it;
        float4 q = *(const float4*)&qkv[base + (size_t)(q0 + m) * QKV_N + qoff + sd];
        uint4 u;
        u.x = __float_as_uint(q.x * 0.125f);
        u.y = __float_as_uint(q.y * 0.125f);
        u.z = __float_as_uint(q.z * 0.125f);
        u.w = __float_as_uint(q.w * 0.125f);
        *(uint4*)&QP[m * 68 + sd] = u;
    }
    __syncthreads();

    // Q a-fragments -> registers (QP becomes P space afterwards)
    unsigned qa[8][4];
#pragma unroll
    for (int ks = 0; ks < 8; ks++)
        ldsm4(qa[ks][0], qa[ks][1], qa[ks][2], qa[ks][3],
              qpBase + (unsigned)(ks * 8) * 4);

    float o[8][4];
    float mr0 = -1e30f, mr1 = -1e30f, l0 = 0.f, l1 = 0.f;
#pragma unroll
    for (int an = 0; an < 8; an++)
#pragma unroll
        for (int r = 0; r < 4; r++) o[an][r] = 0.f;

    const int ktiles = 2 * qt + 2;
    for (int kt = 0; kt < ktiles; kt++) {
        const int n0k = kt * 64;
        const int st  = kt & 1;

        cp_wait<0>();
        __syncthreads();                        // tile kt visible; prev readers done
        if (kt + 1 < ktiles) ATTN_ISSUE(st ^ 1, n0k + 64)

        if (n0k <= q0 + wm0 + 15) {             // skip fully-masked tiles
            const unsigned kBase = smBase + (KS_OFF + (unsigned)(st * 64 + arow) * 68 + acol) * 4;
            const unsigned vRow  = VS_OFF + (unsigned)(st * 64) * 72;

            // ---- S = Q K^T ----
            float s[8][4];
#pragma unroll
            for (int an = 0; an < 8; an++)
#pragma unroll
                for (int r = 0; r < 4; r++) s[an][r] = 0.f;

#pragma unroll
            for (int ks = 0; ks < 8; ks++) {
                const unsigned kofs = (unsigned)(ks * 8) * 4;
#pragma unroll
                for (int p = 0; p < 4; p++) {
                    unsigned b0r, b1r, b2r, b3r;
                    ldsm4(b0r, b1r, b2r, b3r, kBase + (unsigned)(p * 16 * 68) * 4 + kofs);
                    mma8(s[2 * p],     qa[ks], b0r, b2r);
                    mma8(s[2 * p + 1], qa[ks], b1r, b3r);
                }
            }

            // ---- online softmax ----
            const int r0 = q0 + wm0 + g;
            const int r1 = r0 + 8;
            if (n0k + 63 > q0 + wm0) {
#pragma unroll
                for (int an = 0; an < 8; an++) {
                    int c0 = n0k + an * 8 + 2 * t;
                    if (c0 > r0)     s[an][0] = -1e30f;
                    if (c0 + 1 > r0) s[an][1] = -1e30f;
                    if (c0 > r1)     s[an][2] = -1e30f;
                    if (c0 + 1 > r1) s[an][3] = -1e30f;
                }
            }
            float mx0 = -1e30f, mx1 = -1e30f;
#pragma unroll
            for (int an = 0; an < 8; an++) {
                mx0 = fmaxf(mx0, fmaxf(s[an][0], s[an][1]));
                mx1 = fmaxf(mx1, fmaxf(s[an][2], s[an][3]));
            }
            mx0 = fmaxf(mx0, __shfl_xor_sync(0xffffffffu, mx0, 1));
            mx0 = fmaxf(mx0, __shfl_xor_sync(0xffffffffu, mx0, 2));
            mx1 = fmaxf(mx1, __shfl_xor_sync(0xffffffffu, mx1, 1));
            mx1 = fmaxf(mx1, __shfl_xor_sync(0xffffffffu, mx1, 2));

            float mn0 = fmaxf(mr0, mx0), mn1 = fmaxf(mr1, mx1);
            float al0 = __expf(mr0 - mn0), al1 = __expf(mr1 - mn1);
            mr0 = mn0; mr1 = mn1;

            float rs0 = 0.f, rs1 = 0.f;
#pragma unroll
            for (int an = 0; an < 8; an++) {
                float p00 = __expf(s[an][0] - mn0);
                float p01 = __expf(s[an][1] - mn0);
                float p10 = __expf(s[an][2] - mn1);
                float p11 = __expf(s[an][3] - mn1);
                rs0 += p00 + p01;
                rs1 += p10 + p11;
                *(uint2*)&QP[(wm0 + g) * 68 + an * 8 + 2 * t] =
                    make_uint2(f2tf(p00), f2tf(p01));
                *(uint2*)&QP[(wm0 + g + 8) * 68 + an * 8 + 2 * t] =
                    make_uint2(f2tf(p10), f2tf(p11));
#pragma unroll
                for (int r = 0; r < 2; r++) { o[an][r] *= al0; o[an][r + 2] *= al1; }
            }
            rs0 += __shfl_xor_sync(0xffffffffu, rs0, 1);
            rs0 += __shfl_xor_sync(0xffffffffu, rs0, 2);
            rs1 += __shfl_xor_sync(0xffffffffu, rs1, 1);
            rs1 += __shfl_xor_sync(0xffffffffu, rs1, 2);
            l0 = l0 * al0 + rs0;
            l1 = l1 * al1 + rs1;

            __syncwarp();   // P region is warp-private

            // ---- O += P V ----
#pragma unroll
            for (int ks = 0; ks < 8; ks++) {
                const int kv0 = ks * 8;
                unsigned a[4];
                ldsm4(a[0], a[1], a[2], a[3], qpBase + (unsigned)kv0 * 4);
#pragma unroll
                for (int an = 0; an < 8; an++) {
                    unsigned b0 = sm[vRow + (unsigned)(kv0 + t) * 72 + an * 8 + g];
                    unsigned b1 = sm[vRow + (unsigned)(kv0 + t + 4) * 72 + an * 8 + g];
                    mma8(o[an], a, b0, b1);
                }
            }
        }
    }

    // ---- normalize + write (tf32-rounded for the out-projection) ----
    const float inv0 = 1.0f / l0, inv1 = 1.0f / l1;
    const int r0 = q0 + wm0 + g;
#pragma unroll
    for (int an = 0; an < 8; an++) {
        int col = h * HEAD + an * 8 + 2 * t;
        float2 w0 = make_float2(__uint_as_float(f2tf(o[an][0] * inv0)),
                                __uint_as_float(f2tf(o[an][1] * inv0)));
        float2 w1 = make_float2(__uint_as_float(f2tf(o[an][2] * inv1)),
                                __uint_as_float(f2tf(o[an][3] * inv1)));
        *(float2*)&out[((size_t)b * SEQ + r0) * HIDDEN + col]     = w0;
        *(float2*)&out[((size_t)b * SEQ + r0 + 8) * HIDDEN + col] = w1;
    }
}

// ---------------------------------------------------------------------------
extern "C" void kernel_launch(void* const* d_in, const int* in_sizes, int n_in,
                              void* d_out, int out_size)
{
    const float* x     = (const float*)d_in[0];
    const float* W_qkv = (const float*)d_in[1];
    const float* b_qkv = (const float*)d_in[2];
    const float* W_out = (const float*)d_in[3];
    const float* b_out = (const float*)d_in[4];
    float* out = (float*)d_out;

    float *qkv, *att, *xr, *wqkvr, *woutr;
    cudaGetSymbolAddress((void**)&qkv, g_qkv);
    cudaGetSymbolAddress((void**)&att, g_att);
    cudaGetSymbolAddress((void**)&xr, g_xr);
    cudaGetSymbolAddress((void**)&wqkvr, g_wqkvr);
    cudaGetSymbolAddress((void**)&woutr, g_woutr);

    cudaFuncSetAttribute(gemm_tf32,
                         cudaFuncAttributeMaxDynamicSharedMemorySize, GEMM_SMEM);
    cudaFuncSetAttribute(attn_tf32,
                         cudaFuncAttributeMaxDynamicSharedMemorySize, ATTN_SMEM);

    // 0) round inputs to tf32 once
    {
        int n4x = M_TOT * HIDDEN / 4;
        int n4w = HIDDEN * QKV_N / 4;
        int n4o = HIDDEN * HIDDEN / 4;
        round_tf32<<<(n4x + 255) / 256, 256>>>(x, xr, n4x);
        round_tf32<<<(n4w + 255) / 256, 256>>>(W_qkv, wqkvr, n4w);
        round_tf32<<<(n4o + 255) / 256, 256>>>(W_out, woutr, n4o);
    }

    // 1) qkv = x @ W_qkv + b_qkv   (output tf32-rounded)
    gemm_tf32<<<dim3(QKV_N / 128, M_TOT / 128), 256, GEMM_SMEM>>>(
        xr, wqkvr, b_qkv, qkv, M_TOT, QKV_N, HIDDEN, 1);

    // 2) causal flash attention    (output tf32-rounded)
    attn_tf32<<<dim3(SEQ / 128, NH, BATCH), 256, ATTN_SMEM>>>(qkv, att);

    // 3) out = att @ W_out + b_out (raw f32)
    gemm_tf32<<<dim3(HIDDEN / 128, M_TOT / 128), 256, GEMM_SMEM>>>(
        att, woutr, b_out, out, M_TOT, HIDDEN, HIDDEN, 0);
}